// round 2
// baseline (speedup 1.0000x reference)
#include <cuda_runtime.h>

// bicon_loss fused single-kernel:
//   sigmoid (computed once per pixel-channel, shared via row ring buffer)
//   + bilateral voting (8 directional neighbor products)
//   + 3 BCE sums -> scalar, device-wide threadfence reduction.
//
// c_map  f32 [16,8,352,352]
// target f32 [16,1,352,352]
// con    i32 [16,8,352,352]
// out    f32 [1]

#define BB 16
#define HH 352
#define WW 352
#define HW (HH * WW)
#define RPB 16                  // rows per block
#define STRIPS (HH / RPB)       // 22
#define GRID (BB * STRIPS)      // 352 blocks (== blockDim, used in final reduce)
#define WPAD (WW + 2)           // padded row: col 0 and col 353 are permanent zeros

__device__ float        g_part[GRID];
__device__ unsigned int g_cnt = 0;   // reset by last block each run -> graph-replay safe

__device__ __forceinline__ float sigmoid_fast(float x) {
    return __fdividef(1.0f, 1.0f + __expf(-x));
}

// Compute sigmoid row h for all 8 channels: into registers + smem ring slot.
// Out-of-range rows become zeros (matches zero-padded shift semantics).
__device__ __forceinline__ void load_sig_row(
    const float* __restrict__ cmb, int h, int w,
    float (*__restrict__ sprow)[WPAD], float* __restrict__ preg)
{
    if ((unsigned)h < (unsigned)HH) {
        #pragma unroll
        for (int c = 0; c < 8; c++) {
            float x = cmb[c * HW + h * WW + w];
            float p = sigmoid_fast(x);
            preg[c] = p;
            sprow[c][w + 1] = p;
        }
    } else {
        #pragma unroll
        for (int c = 0; c < 8; c++) {
            preg[c] = 0.0f;
            sprow[c][w + 1] = 0.0f;
        }
    }
}

__global__ void __launch_bounds__(WW)
bicon_loss_kernel(const float* __restrict__ c_map,
                  const float* __restrict__ target,
                  const int*   __restrict__ con,
                  float*       __restrict__ out)
{
    // SHIFTS[i] = (dx, dy); vote_i(h,w) = p_i(h,w) * p_{7-i}(h-dy, w-dx)
    const int DXS[8] = { 1, 0, -1, 1, -1, 1, 0, -1 };
    const int DYS[8] = { 1, 1,  1, 0,  0, -1, -1, -1 };
    const float EPSF = 1e-7f;
    const float ONE_M_EPS = 1.0f - 1e-7f;

    __shared__ float sp[3][8][WPAD];   // ring of 3 sigmoid rows x 8 channels
    __shared__ float wsum_f[11];
    __shared__ double wsum_d[11];
    __shared__ bool s_last;

    const int w     = threadIdx.x;           // 0..351
    const int strip = blockIdx.x % STRIPS;
    const int b     = blockIdx.x / STRIPS;
    const int r0    = strip * RPB;

    // permanent zero pad columns (col 0 == logical w=-1, col WPAD-1 == w=WW)
    if (w == 0) {
        #pragma unroll
        for (int s = 0; s < 3; s++)
            #pragma unroll
            for (int c = 0; c < 8; c++) {
                sp[s][c][0] = 0.0f;
                sp[s][c][WPAD - 1] = 0.0f;
            }
    }

    const float* cmb = c_map  + (size_t)b * 8 * HW;
    const int*   cnb = con    + (size_t)b * 8 * HW;
    const float* tgb = target + (size_t)b * HW;

    float pcur[8], pnext[8], pdump[8];

    // slot(h) = (h+1) % 3,  valid for h in [-1, HH]
    load_sig_row(cmb, r0 - 1, w, sp[(r0) % 3],     pdump);
    load_sig_row(cmb, r0,     w, sp[(r0 + 1) % 3], pcur);

    float acc = 0.0f;

    for (int h = r0; h < r0 + RPB; h++) {
        load_sig_row(cmb, h + 1, w, sp[(h + 2) % 3], pnext);
        __syncthreads();

        const int s_m1 = h % 3;          // row h-1
        const int s_0  = (h + 1) % 3;    // row h
        const int s_p1 = (h + 2) % 3;    // row h+1
        const int slots[3] = { s_m1, s_0, s_p1 };

        int t[8];
        #pragma unroll
        for (int i = 0; i < 8; i++)
            t[i] = cnb[i * HW + h * WW + w];

        int sum_conn = 0;
        #pragma unroll
        for (int i = 0; i < 8; i++) sum_conn += t[i];
        const bool edge = (sum_conn > 0) && (sum_conn < 8);

        float lbi = 0.0f, lcon = 0.0f;
        float vmax = -1e30f, vmin = 1e30f;

        #pragma unroll
        for (int i = 0; i < 8; i++) {
            const int dy = DYS[i], dx = DXS[i];
            // neighbor: channel 7-i, row h-dy (slot index 1-dy), col w-dx
            const float s = sp[slots[1 - dy]][7 - i][w + 1 - dx];
            const float v = pcur[i] * s;
            vmax = fmaxf(vmax, v);
            vmin = fminf(vmin, v);

            const float vc = fminf(fmaxf(v,       EPSF), ONE_M_EPS);
            const float pc = fminf(fmaxf(pcur[i], EPSF), ONE_M_EPS);
            const bool tt = (t[i] != 0);
            lbi  -= __logf(tt ? vc : (1.0f - vc));
            lcon -= __logf(tt ? pc : (1.0f - pc));
        }

        const float d  = edge ? (1.0f - vmin) : vmax;
        const float dc = fminf(fmaxf(d, EPSF), ONE_M_EPS);
        const float tg = tgb[h * WW + w];
        const float de = -(tg * __logf(dc) + (1.0f - tg) * __logf(1.0f - dc));

        acc += 0.8f * lcon + de + 0.2f * lbi;

        __syncthreads();   // protect slot of row h-1 before it is overwritten
        #pragma unroll
        for (int c = 0; c < 8; c++) pcur[c] = pnext[c];
    }

    // ---- block reduction (float) ----
    #pragma unroll
    for (int o = 16; o > 0; o >>= 1)
        acc += __shfl_xor_sync(0xffffffffu, acc, o);
    const int lane = w & 31, warp = w >> 5;
    if (lane == 0) wsum_f[warp] = acc;
    __syncthreads();
    if (warp == 0) {
        float v = (lane < 11) ? wsum_f[lane] : 0.0f;
        #pragma unroll
        for (int o = 16; o > 0; o >>= 1)
            v += __shfl_xor_sync(0xffffffffu, v, o);
        if (lane == 0) {
            g_part[blockIdx.x] = v;
            __threadfence();
            unsigned int cnt = atomicAdd(&g_cnt, 1u);
            s_last = (cnt == (unsigned)(GRID - 1));
        }
    }
    __syncthreads();

    // ---- last block: final reduce over GRID partials (double) ----
    if (s_last) {
        __threadfence();
        double v = (double)g_part[w];          // GRID == blockDim == 352
        #pragma unroll
        for (int o = 16; o > 0; o >>= 1)
            v += __shfl_xor_sync(0xffffffffu, v, o);
        if (lane == 0) wsum_d[warp] = v;
        __syncthreads();
        if (warp == 0) {
            double s = (lane < 11) ? wsum_d[lane] : 0.0;
            #pragma unroll
            for (int o = 16; o > 0; o >>= 1)
                s += __shfl_xor_sync(0xffffffffu, s, o);
            if (lane == 0) {
                out[0] = (float)s;
                g_cnt = 0;                      // reset for next graph replay
            }
        }
    }
}

extern "C" void kernel_launch(void* const* d_in, const int* in_sizes, int n_in,
                              void* d_out, int out_size)
{
    const float* c_map  = (const float*)d_in[0];
    const float* target = (const float*)d_in[1];
    const int*   con    = (const int*)  d_in[2];
    float* out = (float*)d_out;

    bicon_loss_kernel<<<GRID, WW>>>(c_map, target, con, out);
}

// round 3
// speedup vs baseline: 1.0204x; 1.0204x over previous
#include <cuda_runtime.h>

// bicon_loss fully-fused single kernel, 4 pixels/thread (float4), log-factored BCE.
// c_map  f32 [16,8,352,352] ; target f32 [16,1,352,352] ; con i32 [16,8,352,352]
// out f32[1]

#define BB 16
#define HH 352
#define WW 352
#define HW (HH * WW)
#define WV (WW / 4)                 // 88 vec-columns
#define NTHREADS (BB * HH * WV)     // 495616
#define TPB 256
#define NBLK (NTHREADS / TPB)       // 1936 exactly

__device__ float        g_part[NBLK];
__device__ unsigned int g_cnt = 0;

__device__ __forceinline__ float sigf(float x) {
    return __fdividef(1.0f, 1.0f + __expf(-x));
}
__device__ __forceinline__ float clipf(float v) {
    return fminf(fmaxf(v, 1e-7f), 1.0f - 1e-7f);
}

__global__ void __launch_bounds__(TPB)
bicon_loss_kernel(const float* __restrict__ c_map,
                  const float* __restrict__ target,
                  const int*   __restrict__ con,
                  float*       __restrict__ out)
{
    const int tid  = blockIdx.x * TPB + threadIdx.x;   // grid covers exactly NTHREADS
    const int wv   = tid % WV;
    const int rest = tid / WV;
    const int h    = rest % HH;
    const int b    = rest / HH;
    const int w0   = wv * 4;

    const float* cmb = c_map + (size_t)b * 8 * HW;
    const int*   cnb = con   + (size_t)b * 8 * HW;
    const size_t roff = (size_t)h * WW + w0;

    const bool wl = (w0 > 0);        // col w0-1 exists
    const bool wr = (wv < WV - 1);   // col w0+4 exists

    // ---- self row: p[c][j] = sigmoid, con bitmask per pixel ----
    float p[8][4];
    unsigned tb[4] = {0u, 0u, 0u, 0u};
    #pragma unroll
    for (int c = 0; c < 8; c++) {
        const float4 x = *(const float4*)(cmb + (size_t)c * HW + roff);
        p[c][0] = sigf(x.x); p[c][1] = sigf(x.y);
        p[c][2] = sigf(x.z); p[c][3] = sigf(x.w);
        const int4 t = *(const int4*)(cnb + (size_t)c * HW + roff);
        tb[0] |= (unsigned)(t.x != 0) << c;
        tb[1] |= (unsigned)(t.y != 0) << c;
        tb[2] |= (unsigned)(t.z != 0) << c;
        tb[3] |= (unsigned)(t.w != 0) << c;
    }
    const float4 tg4 = *(const float4*)(target + (size_t)b * HW + roff);

    // ---- neighbor sigmoids s[i][j]; vote_i(h,w)=p_i(h,w)*p_{7-i}(h-dy,w-dx) ----
    // i: 0..2 -> row h-1 (ch 7,6,5 ; dx 1,0,-1), 3..4 -> row h (ch 4,3 ; dx 1,-1),
    //    5..7 -> row h+1 (ch 2,1,0 ; dx 1,0,-1)
    float s[8][4];

    if (h > 0) {
        const float* r = cmb + roff - WW;
        const float4 u7 = *(const float4*)(r + 7 * HW);
        const float4 u6 = *(const float4*)(r + 6 * HW);
        const float4 u5 = *(const float4*)(r + 5 * HW);
        s[0][0] = wl ? sigf(r[7 * HW - 1]) : 0.0f;
        s[0][1] = sigf(u7.x); s[0][2] = sigf(u7.y); s[0][3] = sigf(u7.z);
        s[1][0] = sigf(u6.x); s[1][1] = sigf(u6.y);
        s[1][2] = sigf(u6.z); s[1][3] = sigf(u6.w);
        s[2][0] = sigf(u5.y); s[2][1] = sigf(u5.z); s[2][2] = sigf(u5.w);
        s[2][3] = wr ? sigf(r[5 * HW + 4]) : 0.0f;
    } else {
        #pragma unroll
        for (int i = 0; i < 3; i++)
            #pragma unroll
            for (int j = 0; j < 4; j++) s[i][j] = 0.0f;
    }

    // row h: ch4 shifted right (needs w0-1), ch3 shifted left (needs w0+4)
    s[3][0] = wl ? sigf(cmb[4 * HW + roff - 1]) : 0.0f;
    s[3][1] = p[4][0]; s[3][2] = p[4][1]; s[3][3] = p[4][2];
    s[4][0] = p[3][1]; s[4][1] = p[3][2]; s[4][2] = p[3][3];
    s[4][3] = wr ? sigf(cmb[3 * HW + roff + 4]) : 0.0f;

    if (h < HH - 1) {
        const float* r = cmb + roff + WW;
        const float4 d2 = *(const float4*)(r + 2 * HW);
        const float4 d1 = *(const float4*)(r + 1 * HW);
        const float4 d0 = *(const float4*)(r + 0 * HW);
        s[5][0] = wl ? sigf(r[2 * HW - 1]) : 0.0f;
        s[5][1] = sigf(d2.x); s[5][2] = sigf(d2.y); s[5][3] = sigf(d2.z);
        s[6][0] = sigf(d1.x); s[6][1] = sigf(d1.y);
        s[6][2] = sigf(d1.z); s[6][3] = sigf(d1.w);
        s[7][0] = sigf(d0.y); s[7][1] = sigf(d0.z); s[7][2] = sigf(d0.w);
        s[7][3] = wr ? sigf(r[4]) : 0.0f;
    } else {
        #pragma unroll
        for (int i = 5; i < 8; i++)
            #pragma unroll
            for (int j = 0; j < 4; j++) s[i][j] = 0.0f;
    }

    // ---- per-pixel losses (log-factored: 6 logs/pixel) ----
    float acc = 0.0f;
    const float tgs[4] = { tg4.x, tg4.y, tg4.z, tg4.w };
    #pragma unroll
    for (int j = 0; j < 4; j++) {
        const unsigned tbj = tb[j];
        const int sc = __popc(tbj);
        const bool edge = (sc > 0) && (sc < 8);

        float vmax = -1e30f, vmin = 1e30f;
        float pb0 = 1.0f, pb1 = 1.0f, pc0 = 1.0f, pc1 = 1.0f;
        #pragma unroll
        for (int i = 0; i < 8; i++) {
            const float v  = p[i][j] * s[i][j];
            vmax = fmaxf(vmax, v);
            vmin = fminf(vmin, v);
            const float vc = clipf(v);
            const float pc = clipf(p[i][j]);
            const bool  tt = (tbj >> i) & 1u;
            const float termb = tt ? vc : (1.0f - vc);
            const float termc = tt ? pc : (1.0f - pc);
            if (i < 4) { pb0 *= termb; pc0 *= termc; }
            else       { pb1 *= termb; pc1 *= termc; }
        }
        const float lbi  = -(__logf(pb0) + __logf(pb1));
        const float lcon = -(__logf(pc0) + __logf(pc1));

        const float d  = edge ? (1.0f - vmin) : vmax;
        const float dc = clipf(d);
        const float tg = tgs[j];
        const float de = -(tg * __logf(dc) + (1.0f - tg) * __logf(1.0f - dc));

        acc += 0.8f * lcon + de + 0.2f * lbi;
    }

    // ---- block reduction ----
    #pragma unroll
    for (int o = 16; o > 0; o >>= 1)
        acc += __shfl_xor_sync(0xffffffffu, acc, o);

    __shared__ float  wsf[8];
    __shared__ double wsd[8];
    __shared__ bool   s_last;
    const int lane = threadIdx.x & 31, warp = threadIdx.x >> 5;
    if (lane == 0) wsf[warp] = acc;
    __syncthreads();
    if (warp == 0) {
        float v = (lane < 8) ? wsf[lane] : 0.0f;
        #pragma unroll
        for (int o = 4; o > 0; o >>= 1)
            v += __shfl_xor_sync(0xffffffffu, v, o);
        if (lane == 0) {
            g_part[blockIdx.x] = v;
            __threadfence();
            const unsigned c = atomicAdd(&g_cnt, 1u);
            s_last = (c == (unsigned)(NBLK - 1));
        }
    }
    __syncthreads();

    // ---- last block: deterministic final reduce in double ----
    if (s_last) {
        __threadfence();
        double v = 0.0;
        for (int i = threadIdx.x; i < NBLK; i += TPB)
            v += (double)g_part[i];
        #pragma unroll
        for (int o = 16; o > 0; o >>= 1)
            v += __shfl_xor_sync(0xffffffffu, v, o);
        if (lane == 0) wsd[warp] = v;
        __syncthreads();
        if (warp == 0) {
            double t = (lane < 8) ? wsd[lane] : 0.0;
            #pragma unroll
            for (int o = 4; o > 0; o >>= 1)
                t += __shfl_xor_sync(0xffffffffu, t, o);
            if (lane == 0) {
                out[0] = (float)t;
                __threadfence();
                g_cnt = 0;   // reset for next graph replay
            }
        }
    }
}

extern "C" void kernel_launch(void* const* d_in, const int* in_sizes, int n_in,
                              void* d_out, int out_size)
{
    const float* c_map  = (const float*)d_in[0];
    const float* target = (const float*)d_in[1];
    const int*   con    = (const int*)  d_in[2];
    bicon_loss_kernel<<<NBLK, TPB>>>(c_map, target, con, (float*)d_out);
}

// round 4
// speedup vs baseline: 1.4121x; 1.3839x over previous
#include <cuda_runtime.h>

// bicon_loss fused single kernel: 1 pixel/thread (register-lean), HW tanh
// sigmoid, log-factored BCE, device-wide threadfence reduction.
// c_map  f32 [16,8,352,352] ; target f32 [16,1,352,352] ; con i32 [16,8,352,352]
// out f32[1]

#define BB 16
#define HH 352
#define WW 352
#define HW (HH * WW)
#define NPIX (BB * HW)          // 1982464
#define TPB 256
#define NBLK (NPIX / TPB)       // 7744 exactly

__device__ float        g_part[NBLK];
__device__ unsigned int g_cnt = 0;

// sigmoid via single-instruction MUFU.TANH: 1/(1+e^-x) = 0.5*tanh(x/2)+0.5
__device__ __forceinline__ float sigf(float x) {
    float t;
    asm("tanh.approx.f32 %0, %1;" : "=f"(t) : "f"(x * 0.5f));
    return fmaf(0.5f, t, 0.5f);
}
__device__ __forceinline__ float clipf(float v) {
    return fminf(fmaxf(v, 1e-7f), 1.0f - 1e-7f);
}

__global__ void __launch_bounds__(TPB)
bicon_loss_kernel(const float* __restrict__ c_map,
                  const float* __restrict__ target,
                  const int*   __restrict__ con,
                  float*       __restrict__ out)
{
    // vote_i(h,w) = p_i(h,w) * p_{7-i}(h-dy_i, w-dx_i), zero outside image
    const int DXS[8] = { 1, 0, -1, 1, -1, 1, 0, -1 };
    const int DYS[8] = { 1, 1,  1, 0,  0, -1, -1, -1 };

    const int idx = blockIdx.x * TPB + threadIdx.x;   // grid covers NPIX exactly
    const int w   = idx % WW;
    const int tmp = idx / WW;
    const int h   = tmp % HH;
    const int b   = tmp / HH;

    const int pixoff = h * WW + w;
    const int cbase  = b * 8 * HW + pixoff;

    // self sigmoids + con bitmask
    float p[8];
    unsigned tb = 0u;
    #pragma unroll
    for (int c = 0; c < 8; c++) {
        p[c] = sigf(c_map[cbase + c * HW]);
        tb |= (unsigned)(con[cbase + c * HW] != 0) << c;
    }

    const int sc = __popc(tb);
    const bool edge = (sc > 0) && (sc < 8);

    float vmax = -1e30f, vmin = 1e30f;
    float pb0 = 1.0f, pb1 = 1.0f, pc0 = 1.0f, pc1 = 1.0f;

    #pragma unroll
    for (int i = 0; i < 8; i++) {
        const int hn = h - DYS[i];
        const int wn = w - DXS[i];
        float s = 0.0f;
        if ((unsigned)hn < (unsigned)HH && (unsigned)wn < (unsigned)WW)
            s = sigf(c_map[(b * 8 + (7 - i)) * HW + hn * WW + wn]);

        const float v = p[i] * s;
        vmax = fmaxf(vmax, v);
        vmin = fminf(vmin, v);

        const float vc = clipf(v);
        const float pc = clipf(p[i]);
        const bool  tt = (tb >> i) & 1u;
        const float termb = tt ? vc : (1.0f - vc);
        const float termc = tt ? pc : (1.0f - pc);
        if (i < 4) { pb0 *= termb; pc0 *= termc; }
        else       { pb1 *= termb; pc1 *= termc; }
    }

    // 6 logs total (2 bi + 2 con + 2 decouple)
    const float lbi  = -(__logf(pb0) + __logf(pb1));
    const float lcon = -(__logf(pc0) + __logf(pc1));

    const float d  = edge ? (1.0f - vmin) : vmax;
    const float dc = clipf(d);
    const float tg = target[b * HW + pixoff];
    const float de = -(tg * __logf(dc) + (1.0f - tg) * __logf(1.0f - dc));

    float acc = fmaf(0.8f, lcon, fmaf(0.2f, lbi, de));

    // ---- block reduction ----
    #pragma unroll
    for (int o = 16; o > 0; o >>= 1)
        acc += __shfl_xor_sync(0xffffffffu, acc, o);

    __shared__ float  wsf[8];
    __shared__ double wsd[8];
    __shared__ bool   s_last;
    const int lane = threadIdx.x & 31, warp = threadIdx.x >> 5;
    if (lane == 0) wsf[warp] = acc;
    __syncthreads();
    if (warp == 0) {
        float v = (lane < 8) ? wsf[lane] : 0.0f;
        #pragma unroll
        for (int o = 4; o > 0; o >>= 1)
            v += __shfl_xor_sync(0xffffffffu, v, o);
        if (lane == 0) {
            g_part[blockIdx.x] = v;
            __threadfence();
            const unsigned c = atomicAdd(&g_cnt, 1u);
            s_last = (c == (unsigned)(NBLK - 1));
        }
    }
    __syncthreads();

    // ---- last block: deterministic final reduce in double ----
    if (s_last) {
        __threadfence();
        double v = 0.0;
        for (int i = threadIdx.x; i < NBLK; i += TPB)
            v += (double)g_part[i];
        #pragma unroll
        for (int o = 16; o > 0; o >>= 1)
            v += __shfl_xor_sync(0xffffffffu, v, o);
        if (lane == 0) wsd[warp] = v;
        __syncthreads();
        if (warp == 0) {
            double t = (lane < 8) ? wsd[lane] : 0.0;
            #pragma unroll
            for (int o = 4; o > 0; o >>= 1)
                t += __shfl_xor_sync(0xffffffffu, t, o);
            if (lane == 0) {
                out[0] = (float)t;
                __threadfence();
                g_cnt = 0;   // reset for next graph replay
            }
        }
    }
}

extern "C" void kernel_launch(void* const* d_in, const int* in_sizes, int n_in,
                              void* d_out, int out_size)
{
    const float* c_map  = (const float*)d_in[0];
    const float* target = (const float*)d_in[1];
    const int*   con    = (const int*)  d_in[2];
    bicon_loss_kernel<<<NBLK, TPB>>>(c_map, target, con, (float*)d_out);
}

// round 5
// speedup vs baseline: 1.4902x; 1.0553x over previous
#include <cuda_runtime.h>

// bicon_loss fused single kernel: 4 pixels/thread (float4/int4), channel-pair
// processing (i, 7-i share opposite shifts) to bound live registers,
// HW tanh sigmoid, log-factored BCE, threadfence reduction.
// c_map f32 [16,8,352,352] ; target f32 [16,1,352,352] ; con i32 [16,8,352,352]

#define BB 16
#define HH 352
#define WW 352
#define HW (HH * WW)
#define WV (WW / 4)              // 88 vec-cols
#define NTH (BB * HH * WV)       // 495616 threads
#define TPB 256
#define NBLK (NTH / TPB)         // 1936 exactly

__device__ float        g_part[NBLK];
__device__ unsigned int g_cnt = 0;

__device__ __forceinline__ float sigf(float x) {
    float t;
    asm("tanh.approx.f32 %0, %1;" : "=f"(t) : "f"(x * 0.5f));
    return fmaf(0.5f, t, 0.5f);
}
__device__ __forceinline__ float clipf(float v) {
    return fminf(fmaxf(v, 1e-7f), 1.0f - 1e-7f);
}

// Pair K: i=K with SHIFT (DX,DY); j=7-K with SHIFT (-DX,-DY).
// vote_i(h,w) = p_i(h,w) * p_j(h-DY, w-DX); vote_j(h,w) = p_j(h,w) * p_i(h+DY, w+DX)
template<int K, int DX, int DY>
__device__ __forceinline__ void do_pair(
    const float* __restrict__ cmb, const int* __restrict__ cnb,
    int h, bool wl, bool wr,
    float* vmax, float* vmin, float* pb0, float* pb1,
    float* pc0, float* pc1, int* scnt)
{
    constexpr int CI = K;
    constexpr int CJ = 7 - K;

    const float4 xi = *(const float4*)(cmb + CI * HW);
    const float4 xj = *(const float4*)(cmb + CJ * HW);
    const float pi[4] = { sigf(xi.x), sigf(xi.y), sigf(xi.z), sigf(xi.w) };
    const float pj[4] = { sigf(xj.x), sigf(xj.y), sigf(xj.z), sigf(xj.w) };

    const int4 ti = *(const int4*)(cnb + CI * HW);
    const int4 tj = *(const int4*)(cnb + CJ * HW);

    float si[4], sj[4];

    if constexpr (DY != 0) {
        // si: channel CJ at row h-DY, cols w0+q-DX
        if ((unsigned)(h - DY) < (unsigned)HH) {
            const float* nb = cmb + CJ * HW - DY * WW;
            const float4 v = *(const float4*)nb;
            if constexpr (DX == 1) {
                si[0] = wl ? sigf(nb[-1]) : 0.0f;
                si[1] = sigf(v.x); si[2] = sigf(v.y); si[3] = sigf(v.z);
            } else if constexpr (DX == 0) {
                si[0] = sigf(v.x); si[1] = sigf(v.y);
                si[2] = sigf(v.z); si[3] = sigf(v.w);
            } else {
                si[0] = sigf(v.y); si[1] = sigf(v.z); si[2] = sigf(v.w);
                si[3] = wr ? sigf(nb[4]) : 0.0f;
            }
        } else { si[0] = si[1] = si[2] = si[3] = 0.0f; }

        // sj: channel CI at row h+DY, cols w0+q+DX
        if ((unsigned)(h + DY) < (unsigned)HH) {
            const float* nb = cmb + CI * HW + DY * WW;
            const float4 v = *(const float4*)nb;
            if constexpr (DX == 1) {
                sj[0] = sigf(v.y); sj[1] = sigf(v.z); sj[2] = sigf(v.w);
                sj[3] = wr ? sigf(nb[4]) : 0.0f;
            } else if constexpr (DX == 0) {
                sj[0] = sigf(v.x); sj[1] = sigf(v.y);
                sj[2] = sigf(v.z); sj[3] = sigf(v.w);
            } else {
                sj[0] = wl ? sigf(nb[-1]) : 0.0f;
                sj[1] = sigf(v.x); sj[2] = sigf(v.y); sj[3] = sigf(v.z);
            }
        } else { sj[0] = sj[1] = sj[2] = sj[3] = 0.0f; }
    } else {
        // K==3 (DX=1, DY=0): row-h shifts reuse self sigmoids
        si[0] = wl ? sigf(cmb[CJ * HW - 1]) : 0.0f;
        si[1] = pj[0]; si[2] = pj[1]; si[3] = pj[2];
        sj[0] = pi[1]; sj[1] = pi[2]; sj[2] = pi[3];
        sj[3] = wr ? sigf(cmb[CI * HW + 4]) : 0.0f;
    }

    const int tia[4] = { ti.x, ti.y, ti.z, ti.w };
    const int tja[4] = { tj.x, tj.y, tj.z, tj.w };
    #pragma unroll
    for (int q = 0; q < 4; q++) {
        const float vi = pi[q] * si[q];
        const float vj = pj[q] * sj[q];
        vmax[q] = fmaxf(vmax[q], fmaxf(vi, vj));
        vmin[q] = fminf(vmin[q], fminf(vi, vj));
        const bool bi = (tia[q] != 0);
        const bool bj = (tja[q] != 0);
        scnt[q] += (int)bi + (int)bj;
        // 1 - clip(v) == clip(1 - v): select first, clip once
        pb0[q] *= clipf(bi ? vi    : 1.0f - vi);
        pb1[q] *= clipf(bj ? vj    : 1.0f - vj);
        pc0[q] *= clipf(bi ? pi[q] : 1.0f - pi[q]);
        pc1[q] *= clipf(bj ? pj[q] : 1.0f - pj[q]);
    }
}

__global__ void __launch_bounds__(TPB, 4)
bicon_loss_kernel(const float* __restrict__ c_map,
                  const float* __restrict__ target,
                  const int*   __restrict__ con,
                  float*       __restrict__ out)
{
    const int tid  = blockIdx.x * TPB + threadIdx.x;   // grid covers NTH exactly
    const int wv   = tid % WV;
    const int rest = tid / WV;
    const int h    = rest % HH;
    const int b    = rest / HH;
    const int w0   = wv * 4;

    const size_t roff = (size_t)h * WW + w0;
    const float* cmb = c_map + (size_t)b * 8 * HW + roff;
    const int*   cnb = con   + (size_t)b * 8 * HW + roff;
    const bool wl = (w0 > 0);
    const bool wr = (wv < WV - 1);

    float vmax[4] = { -1e30f, -1e30f, -1e30f, -1e30f };
    float vmin[4] = {  1e30f,  1e30f,  1e30f,  1e30f };
    float pb0[4]  = { 1.f, 1.f, 1.f, 1.f };
    float pb1[4]  = { 1.f, 1.f, 1.f, 1.f };
    float pc0[4]  = { 1.f, 1.f, 1.f, 1.f };
    float pc1[4]  = { 1.f, 1.f, 1.f, 1.f };
    int   scnt[4] = { 0, 0, 0, 0 };

    // SHIFTS: k=0:(1,1)  k=1:(0,1)  k=2:(-1,1)  k=3:(1,0)
    do_pair<0,  1, 1>(cmb, cnb, h, wl, wr, vmax, vmin, pb0, pb1, pc0, pc1, scnt);
    do_pair<1,  0, 1>(cmb, cnb, h, wl, wr, vmax, vmin, pb0, pb1, pc0, pc1, scnt);
    do_pair<2, -1, 1>(cmb, cnb, h, wl, wr, vmax, vmin, pb0, pb1, pc0, pc1, scnt);
    do_pair<3,  1, 0>(cmb, cnb, h, wl, wr, vmax, vmin, pb0, pb1, pc0, pc1, scnt);

    const float4 tg4 = *(const float4*)(target + (size_t)b * HW + roff);
    const float tgs[4] = { tg4.x, tg4.y, tg4.z, tg4.w };

    float acc = 0.0f;
    #pragma unroll
    for (int q = 0; q < 4; q++) {
        const bool edge = (scnt[q] > 0) && (scnt[q] < 8);
        const float lbi  = -(__logf(pb0[q]) + __logf(pb1[q]));
        const float lcon = -(__logf(pc0[q]) + __logf(pc1[q]));
        const float d  = edge ? (1.0f - vmin[q]) : vmax[q];
        const float dc = clipf(d);
        const float tg = tgs[q];
        const float de = -(tg * __logf(dc) + (1.0f - tg) * __logf(1.0f - dc));
        acc += fmaf(0.8f, lcon, fmaf(0.2f, lbi, de));
    }

    // ---- block reduction ----
    #pragma unroll
    for (int o = 16; o > 0; o >>= 1)
        acc += __shfl_xor_sync(0xffffffffu, acc, o);

    __shared__ float  wsf[8];
    __shared__ double wsd[8];
    __shared__ bool   s_last;
    const int lane = threadIdx.x & 31, warp = threadIdx.x >> 5;
    if (lane == 0) wsf[warp] = acc;
    __syncthreads();
    if (warp == 0) {
        float v = (lane < 8) ? wsf[lane] : 0.0f;
        #pragma unroll
        for (int o = 4; o > 0; o >>= 1)
            v += __shfl_xor_sync(0xffffffffu, v, o);
        if (lane == 0) {
            g_part[blockIdx.x] = v;
            __threadfence();
            const unsigned c = atomicAdd(&g_cnt, 1u);
            s_last = (c == (unsigned)(NBLK - 1));
        }
    }
    __syncthreads();

    // ---- last block: deterministic final reduce in double ----
    if (s_last) {
        __threadfence();
        double v = 0.0;
        for (int i = threadIdx.x; i < NBLK; i += TPB)
            v += (double)g_part[i];
        #pragma unroll
        for (int o = 16; o > 0; o >>= 1)
            v += __shfl_xor_sync(0xffffffffu, v, o);
        if (lane == 0) wsd[warp] = v;
        __syncthreads();
        if (warp == 0) {
            double t = (lane < 8) ? wsd[lane] : 0.0;
            #pragma unroll
            for (int o = 4; o > 0; o >>= 1)
                t += __shfl_xor_sync(0xffffffffu, t, o);
            if (lane == 0) {
                out[0] = (float)t;
                __threadfence();
                g_cnt = 0;   // reset for next graph replay
            }
        }
    }
}

extern "C" void kernel_launch(void* const* d_in, const int* in_sizes, int n_in,
                              void* d_out, int out_size)
{
    const float* c_map  = (const float*)d_in[0];
    const float* target = (const float*)d_in[1];
    const int*   con    = (const int*)  d_in[2];
    bicon_loss_kernel<<<NBLK, TPB>>>(c_map, target, con, (float*)d_out);
}